// round 14
// baseline (speedup 1.0000x reference)
#include <cuda_runtime.h>
#include <cuda_fp16.h>
#include <math.h>
#include <stdint.h>

#define BSZ 16
#define CC  256
#define SSZ 1024
#define NHD 8
#define NG  16
#define CPG 16
#define EPSV 1e-5f

// scale(1/sqrt(256)) * log2(e), folded into Q at qkv-GEMM epilogue
#define QSC 0.09016844005556021f

__device__ __align__(128) float  g_norm  [2 * BSZ * CC * SSZ];
__device__ __align__(128) __half g_normh [2 * BSZ * CC * SSZ];
__device__ __align__(128) __half g_qkvh  [2 * BSZ * 3 * CC * SSZ];
__device__ __align__(128) __half g_attnh [2 * BSZ * CC * SSZ];
__device__ __align__(128) __half g_wh    [2 * 3 * CC * CC + 2 * CC * CC];

__device__ __forceinline__ uint32_t packh(float lo, float hi) {
    __half2 h = __floats2half2_rn(lo, hi);
    return *(uint32_t*)&h;
}
__device__ __forceinline__ uint32_t ex2h2(uint32_t x) {
    uint32_t y;
    asm("ex2.approx.f16x2 %0, %1;" : "=r"(y) : "r"(x));
    return y;
}
__device__ __forceinline__ uint32_t hadd2u(uint32_t a, uint32_t b) {
    uint32_t y;
    asm("add.f16x2 %0, %1, %2;" : "=r"(y) : "r"(a), "r"(b));
    return y;
}
// fp16 inputs, fp32 accumulate
__device__ __forceinline__ void mma_f16(float d[4], const uint32_t a[4],
                                        const uint32_t b[2]) {
    asm volatile(
        "mma.sync.aligned.m16n8k16.row.col.f32.f16.f16.f32 "
        "{%0,%1,%2,%3}, {%4,%5,%6,%7}, {%8,%9}, {%0,%1,%2,%3};\n"
        : "+f"(d[0]), "+f"(d[1]), "+f"(d[2]), "+f"(d[3])
        : "r"(a[0]), "r"(a[1]), "r"(a[2]), "r"(a[3]), "r"(b[0]), "r"(b[1]));
}
// fp16 inputs, fp16 accumulate (C frag = 2 x f16x2 regs)
__device__ __forceinline__ void mma_f16acc(uint32_t d[2], const uint32_t a[4],
                                           const uint32_t b[2]) {
    asm volatile(
        "mma.sync.aligned.m16n8k16.row.col.f16.f16.f16.f16 "
        "{%0,%1}, {%2,%3,%4,%5}, {%6,%7}, {%0,%1};\n"
        : "+r"(d[0]), "+r"(d[1])
        : "r"(a[0]), "r"(a[1]), "r"(a[2]), "r"(a[3]), "r"(b[0]), "r"(b[1]));
}
__device__ __forceinline__ void ldmx4(uint32_t r[4], uint32_t addr) {
    asm volatile("ldmatrix.sync.aligned.m8n8.x4.shared.b16 {%0,%1,%2,%3}, [%4];"
                 : "=r"(r[0]), "=r"(r[1]), "=r"(r[2]), "=r"(r[3]) : "r"(addr));
}
__device__ __forceinline__ void ldmx4t(uint32_t r[4], uint32_t addr) {
    asm volatile("ldmatrix.sync.aligned.m8n8.x4.trans.shared.b16 {%0,%1,%2,%3}, [%4];"
                 : "=r"(r[0]), "=r"(r[1]), "=r"(r[2]), "=r"(r[3]) : "r"(addr));
}
__device__ __forceinline__ void cpa16(uint32_t dst, const void* src) {
    asm volatile("cp.async.cg.shared.global [%0], [%1], 16;\n"
                 :: "r"(dst), "l"(src));
}
#define CP_COMMIT() asm volatile("cp.async.commit_group;\n" ::)
#define CP_WAIT(n)  asm volatile("cp.async.wait_group %0;\n" :: "n"(n))

// ---------------------------------------------------------------------------
// All four weight conversions in ONE launch (fp32 -> fp16)
// ---------------------------------------------------------------------------
__global__ void cvt_all(const float* __restrict__ wqkvA,
                        const float* __restrict__ wqkvB,
                        const float* __restrict__ woutA,
                        const float* __restrict__ woutB,
                        __half* __restrict__ dq,
                        __half* __restrict__ do_) {
    int i = blockIdx.x * blockDim.x + threadIdx.x;
    const int QW = 3 * CC * CC / 4;
    const int OW = CC * CC / 4;
    const float* s; __half* d; int off;
    if (i < QW)               { s = wqkvA; d = dq;               off = i; }
    else if (i < 2 * QW)      { s = wqkvB; d = dq + 4 * QW;      off = i - QW; }
    else if (i < 2 * QW + OW) { s = woutA; d = do_;              off = i - 2 * QW; }
    else                      { s = woutB; d = do_ + 4 * OW;     off = i - 2 * QW - OW; }
    float4 v = ((const float4*)s)[off];
    *(uint2*)(d + (size_t)off * 4) = make_uint2(packh(v.x, v.y), packh(v.z, v.w));
}

// ---------------------------------------------------------------------------
// GroupNorm, both branches in one launch, x cached in registers (1 read)
// ---------------------------------------------------------------------------
__global__ void groupnorm_kernel(const float* __restrict__ x0,
                                 const float* __restrict__ x1,
                                 const float* __restrict__ gm0,
                                 const float* __restrict__ gm1,
                                 const float* __restrict__ bt0,
                                 const float* __restrict__ bt1,
                                 float* __restrict__ out,
                                 __half* __restrict__ outh) {
    int br = blockIdx.y;
    const float* x     = br ? x1 : x0;
    const float* gamma = br ? gm1 : gm0;
    const float* beta  = br ? bt1 : bt0;
    size_t broff = (size_t)br * BSZ * CC * SSZ;

    int bg = blockIdx.x;
    int b = bg / NG, g = bg % NG;
    const int n = CPG * SSZ;
    size_t off = broff + (size_t)(b * CC + g * CPG) * SSZ;
    int tid = threadIdx.x;

    const float4* x4 = (const float4*)(x + (size_t)(b * CC + g * CPG) * SSZ);
    float4 xv[16];
    float s = 0.f, s2 = 0.f;
    #pragma unroll
    for (int r = 0; r < 16; r++) {
        float4 v = x4[tid + r * 256];
        xv[r] = v;
        s  += v.x + v.y + v.z + v.w;
        s2 += v.x * v.x + v.y * v.y + v.z * v.z + v.w * v.w;
    }
    __shared__ float rs[256], rs2[256];
    rs[tid] = s; rs2[tid] = s2;
    __syncthreads();
    for (int o = 128; o > 0; o >>= 1) {
        if (tid < o) { rs[tid] += rs[tid + o]; rs2[tid] += rs2[tid + o]; }
        __syncthreads();
    }
    float mu = rs[0] / (float)n;
    float var = rs2[0] / (float)n - mu * mu;
    float rstd = rsqrtf(var + EPSV);

    float4* o4 = (float4*)(out + off);
    __half* oh = outh + off;
    #pragma unroll
    for (int r = 0; r < 16; r++) {
        int i = tid + r * 256;
        int c = g * CPG + (i >> 8);
        float sc = gamma[c] * rstd;
        float sh = beta[c] - mu * sc;
        float4 v = xv[r];
        float4 rr;
        rr.x = v.x * sc + sh; rr.y = v.y * sc + sh;
        rr.z = v.z * sc + sh; rr.w = v.w * sc + sh;
        o4[i] = rr;
        *(uint2*)(oh + (size_t)i * 4) =
            make_uint2(packh(rr.x, rr.y), packh(rr.z, rr.w));
    }
}

// ---------------------------------------------------------------------------
// fp16 GEMM, cp.async 3-stage. C = A[Mx256]*B[256x1024]. z = branch*16+batch.
// ---------------------------------------------------------------------------
#define GA_BYTES (128 * 80)
#define GB_BYTES (32 * 272)
#define GBUF (GA_BYTES + GB_BYTES)
#define GEMM_SMEM (3 * GBUF)

__device__ __forceinline__ void gemm_stage(uint32_t sbuf,
                                           const __half* A,
                                           const __half* Bp,
                                           int m0, int n0, int k0, int tid) {
    #pragma unroll
    for (int r = 0; r < 2; r++) {
        int idx = tid + r * 256;
        int row = idx >> 2, ch = idx & 3;
        cpa16(sbuf + row * 80 + ch * 16,
              A + (size_t)(m0 + row) * 256 + k0 + ch * 8);
    }
    #pragma unroll
    for (int r = 0; r < 2; r++) {
        int idx = tid + r * 256;
        int krow = idx >> 4, ch = idx & 15;
        cpa16(sbuf + GA_BYTES + krow * 272 + ch * 16,
              Bp + (size_t)(k0 + krow) * 1024 + n0 + ch * 8);
    }
}

template <bool EPI>
__global__ __launch_bounds__(256, 2) void gemm_f16(
    const __half* __restrict__ A0, const __half* __restrict__ A1,
    const __half* __restrict__ B0, const __half* __restrict__ B1,
    void* __restrict__ C0, void* __restrict__ C1,
    const float* __restrict__ bias0, const float* __restrict__ bias1,
    const float* __restrict__ res0, const float* __restrict__ res1,
    long strideB, long strideC) {
    const int N = 1024;
    int z = blockIdx.z;
    int br = z >> 4, bz = z & 15;
    const __half* A = br ? A1 : A0;
    const __half* Bp = (br ? B1 : B0) + (size_t)bz * strideB;
    int m0 = blockIdx.y * 128, n0 = blockIdx.x * 128;

    extern __shared__ __align__(16) uint8_t smem[];
    uint32_t sbase = (uint32_t)__cvta_generic_to_shared(smem);

    int tid = threadIdx.x;
    int lane = tid & 31, wid = tid >> 5;
    int wy = wid >> 2, wx = wid & 3;
    int lq = lane >> 2, lr = lane & 3;
    int l7 = lane & 7, lb = (lane >> 3) & 1, lhi = lane >> 4;

    float acc[4][4][4];
    #pragma unroll
    for (int i = 0; i < 4; i++)
        #pragma unroll
        for (int j = 0; j < 4; j++)
            #pragma unroll
            for (int c = 0; c < 4; c++) acc[i][j][c] = 0.f;

    gemm_stage(sbase, A, Bp, m0, n0, 0, tid);  CP_COMMIT();
    gemm_stage(sbase + GBUF, A, Bp, m0, n0, 32, tid);  CP_COMMIT();

    #pragma unroll
    for (int it = 0; it < 8; it++) {
        if (it == 7) { CP_WAIT(0); } else { CP_WAIT(1); }
        __syncthreads();
        if (it < 6) {
            gemm_stage(sbase + ((it + 2) % 3) * GBUF, A, Bp, m0, n0,
                       (it + 2) * 32, tid);
            CP_COMMIT();
        }
        uint32_t sA = sbase + (it % 3) * GBUF;
        uint32_t sB = sA + GA_BYTES;
        #pragma unroll
        for (int kk = 0; kk < 2; kk++) {
            uint32_t af[4][4], bf[2][4];
            #pragma unroll
            for (int mi = 0; mi < 4; mi++) {
                int row = wy * 64 + mi * 16 + l7 + lb * 8;
                int col = kk * 16 + lhi * 8;
                ldmx4(af[mi], sA + row * 80 + col * 2);
            }
            #pragma unroll
            for (int njp = 0; njp < 2; njp++) {
                int row = kk * 16 + l7 + lb * 8;
                int col = wx * 32 + njp * 16 + lhi * 8;
                ldmx4t(bf[njp], sB + row * 272 + col * 2);
            }
            #pragma unroll
            for (int mi = 0; mi < 4; mi++)
                #pragma unroll
                for (int njp = 0; njp < 2; njp++) {
                    mma_f16(acc[mi][njp * 2],     af[mi], &bf[njp][0]);
                    mma_f16(acc[mi][njp * 2 + 1], af[mi], &bf[njp][2]);
                }
        }
    }

    if (EPI) {
        float* Cp = (float*)(br ? C1 : C0) + (size_t)bz * strideC;
        const float* bias = br ? bias1 : bias0;
        const float* Rp = (br ? res1 : res0) + (size_t)bz * strideB;
        #pragma unroll
        for (int mi = 0; mi < 4; mi++) {
            #pragma unroll
            for (int nj = 0; nj < 4; nj++) {
                int m = m0 + wy * 64 + mi * 16 + lq;
                int col = n0 + wx * 32 + nj * 8 + (lr << 1);
                float b0 = bias[m], b1 = bias[m + 8];
                float2 r0 = *(const float2*)(Rp + (size_t)m * N + col);
                float2 r1 = *(const float2*)(Rp + (size_t)(m + 8) * N + col);
                *(float2*)(Cp + (size_t)m * N + col) =
                    make_float2(acc[mi][nj][0] + b0 + r0.x,
                                acc[mi][nj][1] + b0 + r0.y);
                *(float2*)(Cp + (size_t)(m + 8) * N + col) =
                    make_float2(acc[mi][nj][2] + b1 + r1.x,
                                acc[mi][nj][3] + b1 + r1.y);
            }
        }
    } else {
        __half* Cp = (__half*)(br ? C1 : C0) + (size_t)bz * strideC;
        #pragma unroll
        for (int mi = 0; mi < 4; mi++) {
            #pragma unroll
            for (int nj = 0; nj < 4; nj++) {
                int m = m0 + wy * 64 + mi * 16 + lq;
                int col = n0 + wx * 32 + nj * 8 + (lr << 1);
                float q0 = ((m % 96) < 32) ? QSC : 1.f;
                float q1 = (((m + 8) % 96) < 32) ? QSC : 1.f;
                *(uint32_t*)(Cp + (size_t)m * N + col) =
                    packh(acc[mi][nj][0] * q0, acc[mi][nj][1] * q0);
                *(uint32_t*)(Cp + (size_t)(m + 8) * N + col) =
                    packh(acc[mi][nj][2] * q1, acc[mi][nj][3] * q1);
            }
        }
    }
}

// ---------------------------------------------------------------------------
// fp16 flash attention: fused per-16-kpos chunks, S in f16-acc, exp in-place
// via ex2.approx.f16x2. l accumulated on the FMA pipe (HADD2 in f16x2,
// flushed to fp32 per k-tile) -- tensor pipe carries ONLY the 64 math MMAs.
// ---------------------------------------------------------------------------
#define ATT_T   8704
#define ATT_SMEM (ATT_T + 3 * 2 * ATT_T)

__device__ __forceinline__ void attn_stage_kv(uint32_t sK,
                                              const __half* Kg,
                                              const __half* Vg,
                                              int k0c, int tid) {
    #pragma unroll
    for (int r = 0; r < 2; r++) {
        int idx = tid + r * 256;
        int row = idx >> 4, ch = idx & 15;
        cpa16(sK + row * 272 + ch * 16,
              Kg + (size_t)row * SSZ + k0c + ch * 8);
        cpa16(sK + ATT_T + row * 272 + ch * 16,
              Vg + (size_t)row * SSZ + k0c + ch * 8);
    }
}

__global__ __launch_bounds__(256, 3) void attn_f16(
    const __half* __restrict__ qkvA,
    const __half* __restrict__ qkvB,
    __half* __restrict__ attnA,
    __half* __restrict__ attnB) {
    extern __shared__ __align__(16) uint8_t smraw[];
    uint32_t sQ = (uint32_t)__cvta_generic_to_shared(smraw);

    int brz = blockIdx.z;
    const __half* qsrc = brz ? qkvA : qkvB;
    const __half* kvsrc = brz ? qkvB : qkvA;
    __half* outh = brz ? attnB : attnA;

    int qt = blockIdx.x;
    int bh = blockIdx.y;
    int b = bh >> 3, h = bh & 7;
    size_t base = (size_t)b * 3 * CC * SSZ + (size_t)h * 96 * SSZ;
    const __half* Qg = qsrc  + base;
    const __half* Kg = kvsrc + base + 32 * SSZ;
    const __half* Vg = kvsrc + base + 64 * SSZ;

    int tid = threadIdx.x;
    int lane = tid & 31, wid = tid >> 5;
    int lq = lane >> 2, lr = lane & 3;
    int l7 = lane & 7, lb = (lane >> 3) & 1, lhi = lane >> 4;
    int q0 = qt * 128;

    // group0 = Q + KV0 ; group1 = KV1
    #pragma unroll
    for (int r = 0; r < 2; r++) {
        int idx = tid + r * 256;
        int row = idx >> 4, ch = idx & 15;
        cpa16(sQ + row * 272 + ch * 16, Qg + (size_t)row * SSZ + q0 + ch * 8);
    }
    attn_stage_kv(sQ + ATT_T, Kg, Vg, 0, tid);
    CP_COMMIT();
    attn_stage_kv(sQ + ATT_T + 2 * ATT_T, Kg, Vg, 128, tid);
    CP_COMMIT();

    // Q ready after group0 completes
    CP_WAIT(1);
    __syncthreads();
    uint32_t qf[2][4];
    #pragma unroll
    for (int kk = 0; kk < 2; kk++) {
        int row = kk * 16 + l7 + lhi * 8;        // d
        int col = wid * 16 + lb * 8;             // q
        ldmx4t(qf[kk], sQ + row * 272 + col * 2);
    }

    float l0 = 0.f, l1 = 0.f;
    float oacc[4][4];
    #pragma unroll
    for (int j = 0; j < 4; j++)
        #pragma unroll
        for (int c = 0; c < 4; c++) oacc[j][c] = 0.f;

    for (int kt = 0; kt < 8; kt++) {
        if (kt > 0) {
            if (kt == 7) { CP_WAIT(0); } else { CP_WAIT(1); }
            __syncthreads();
        }
        if (kt < 6) {
            attn_stage_kv(sQ + ATT_T + ((kt + 2) % 3) * 2 * ATT_T,
                          Kg, Vg, (kt + 2) * 128, tid);
            CP_COMMIT();
        }
        uint32_t sK = sQ + ATT_T + (kt % 3) * 2 * ATT_T;
        uint32_t sV = sK + ATT_T;

        // per-tile f16x2 row-sum accumulators (max 16 vals/half <= 256: safe)
        uint32_t lh0 = 0u, lh1 = 0u;

        // Fused per-chunk pipeline: 16 kpos per njp.
        #pragma unroll
        for (int njp = 0; njp < 8; njp++) {
            uint32_t s0[2] = {0u, 0u};
            uint32_t s1[2] = {0u, 0u};
            #pragma unroll
            for (int kk = 0; kk < 2; kk++) {
                uint32_t kf[4];
                int krow = kk * 16 + l7 + lb * 8;
                int col = njp * 16 + lhi * 8;
                ldmx4t(kf, sK + krow * 272 + col * 2);
                mma_f16acc(s0, qf[kk], &kf[0]);
                mma_f16acc(s1, qf[kk], &kf[2]);
            }
            // p = 2^s directly in f16x2: S C-frag IS the O A-frag layout
            uint32_t af[4];
            af[0] = ex2h2(s0[0]);
            af[1] = ex2h2(s0[1]);
            af[2] = ex2h2(s1[0]);
            af[3] = ex2h2(s1[1]);

            // l-row-sums on the FMA pipe (af[0],af[2] -> row lq; af[1],af[3]
            // -> row lq+8)
            lh0 = hadd2u(lh0, hadd2u(af[0], af[2]));
            lh1 = hadd2u(lh1, hadd2u(af[1], af[3]));

            int col = njp * 16 + lb * 8;         // kpos
            int rbase = l7 + lhi * 8;            // d
            uint32_t vf0[4], vf1[4];
            ldmx4(vf0, sV + rbase * 272 + col * 2);
            ldmx4(vf1, sV + (rbase + 16) * 272 + col * 2);
            mma_f16(oacc[0], af, &vf0[0]);
            mma_f16(oacc[1], af, &vf0[2]);
            mma_f16(oacc[2], af, &vf1[0]);
            mma_f16(oacc[3], af, &vf1[2]);
        }

        // flush tile sums to fp32
        __half2 h0 = *(__half2*)&lh0, h1 = *(__half2*)&lh1;
        l0 += __half2float(h0.x) + __half2float(h0.y);
        l1 += __half2float(h1.x) + __half2float(h1.y);
    }

    // reduce l across the 4 lanes of each row quad
    l0 += __shfl_xor_sync(0xffffffffu, l0, 1);
    l0 += __shfl_xor_sync(0xffffffffu, l0, 2);
    l1 += __shfl_xor_sync(0xffffffffu, l1, 1);
    l1 += __shfl_xor_sync(0xffffffffu, l1, 2);
    float il0 = 1.f / l0, il1 = 1.f / l1;

    __half* O16 = (__half*)smraw;   // [32][136]
    int r0g = wid * 16 + lq;
    __syncthreads();
    #pragma unroll
    for (int nj = 0; nj < 4; nj++) {
        int d0 = nj * 8 + (lr << 1);
        O16[d0 * 136 + r0g]           = __float2half(oacc[nj][0] * il0);
        O16[(d0 + 1) * 136 + r0g]     = __float2half(oacc[nj][1] * il0);
        O16[d0 * 136 + r0g + 8]       = __float2half(oacc[nj][2] * il1);
        O16[(d0 + 1) * 136 + r0g + 8] = __float2half(oacc[nj][3] * il1);
    }
    __syncthreads();
    #pragma unroll
    for (int r = 0; r < 2; r++) {
        int idx = tid + r * 256;
        int row = idx >> 4, ch = idx & 15;
        *(uint4*)(outh + ((size_t)b * CC + h * 32 + row) * SSZ + q0 + ch * 8) =
            *(uint4*)&O16[row * 136 + ch * 8];
    }
}

// ---------------------------------------------------------------------------
extern "C" void kernel_launch(void* const* d_in, const int* in_sizes, int n_in,
                              void* d_out, int out_size) {
    const float* xA    = (const float*)d_in[0];
    const float* xB    = (const float*)d_in[1];
    const float* gA    = (const float*)d_in[2];
    const float* bA    = (const float*)d_in[3];
    const float* gB    = (const float*)d_in[4];
    const float* bB    = (const float*)d_in[5];
    const float* WqkvA = (const float*)d_in[6];
    const float* WqkvB = (const float*)d_in[7];
    const float* WoutA = (const float*)d_in[8];
    const float* boutA = (const float*)d_in[9];
    const float* WoutB = (const float*)d_in[10];
    const float* boutB = (const float*)d_in[11];
    float* out = (float*)d_out;

    void *pn, *pnh, *pq, *pa, *pw;
    cudaGetSymbolAddress(&pn,  g_norm);
    cudaGetSymbolAddress(&pnh, g_normh);
    cudaGetSymbolAddress(&pq,  g_qkvh);
    cudaGetSymbolAddress(&pa,  g_attnh);
    cudaGetSymbolAddress(&pw,  g_wh);
    float* normA = (float*)pn;
    float* normB = normA + (size_t)BSZ * CC * SSZ;
    __half* normhA = (__half*)pnh;
    __half* normhB = normhA + (size_t)BSZ * CC * SSZ;
    __half* qkvA = (__half*)pq;
    __half* qkvB = qkvA + (size_t)BSZ * 3 * CC * SSZ;
    __half* attnA = (__half*)pa;
    __half* attnB = attnA + (size_t)BSZ * CC * SSZ;
    __half* wqA = (__half*)pw;
    __half* wqB = wqA + 3 * CC * CC;
    __half* woA = wqB + 3 * CC * CC;
    __half* woB = woA + CC * CC;

    const long CS = (long)CC * SSZ;
    const long Q3 = (long)3 * CC * SSZ;

    cudaFuncSetAttribute(gemm_f16<false>,
                         cudaFuncAttributeMaxDynamicSharedMemorySize, GEMM_SMEM);
    cudaFuncSetAttribute(gemm_f16<true>,
                         cudaFuncAttributeMaxDynamicSharedMemorySize, GEMM_SMEM);
    cudaFuncSetAttribute(attn_f16,
                         cudaFuncAttributeMaxDynamicSharedMemorySize, ATT_SMEM);

    cvt_all<<<512, 256>>>(WqkvA, WqkvB, WoutA, WoutB, wqA, woA);

    dim3 gn(BSZ * NG, 2);
    groupnorm_kernel<<<gn, 256>>>(xA, xB, gA, gB, bA, bB,
                                  normA, (__half*)pnh);

    dim3 gq(8, 6, 32);
    gemm_f16<false><<<gq, 256, GEMM_SMEM>>>(
        wqA, wqB, normhA, normhB, qkvA, qkvB,
        nullptr, nullptr, nullptr, nullptr, CS, Q3);

    dim3 ga(8, BSZ * NHD, 2);
    attn_f16<<<ga, 256, ATT_SMEM>>>(qkvA, qkvB, attnA, attnB);

    dim3 gp(8, 2, 32);
    gemm_f16<true><<<gp, 256, GEMM_SMEM>>>(
        woA, woB, attnA, attnB, out, out + (size_t)BSZ * CC * SSZ,
        boutA, boutB, normA, normB, CS, CS);
}

// round 15
// speedup vs baseline: 1.0485x; 1.0485x over previous
#include <cuda_runtime.h>
#include <cuda_fp16.h>
#include <math.h>
#include <stdint.h>

#define BSZ 16
#define CC  256
#define SSZ 1024
#define NHD 8
#define NG  16
#define CPG 16
#define EPSV 1e-5f

// scale(1/sqrt(256)) * log2(e), folded into Q at qkv-GEMM epilogue
#define QSC 0.09016844005556021f

__device__ __align__(128) __half g_normh [2 * BSZ * CC * SSZ];
__device__ __align__(128) __half g_qkvh  [2 * BSZ * 3 * CC * SSZ];
__device__ __align__(128) __half g_attnh [2 * BSZ * CC * SSZ];
__device__ __align__(128) __half g_wh    [2 * 3 * CC * CC + 2 * CC * CC];

__device__ __forceinline__ uint32_t packh(float lo, float hi) {
    __half2 h = __floats2half2_rn(lo, hi);
    return *(uint32_t*)&h;
}
__device__ __forceinline__ uint32_t ex2h2(uint32_t x) {
    uint32_t y;
    asm("ex2.approx.f16x2 %0, %1;" : "=r"(y) : "r"(x));
    return y;
}
// fp16 inputs, fp32 accumulate
__device__ __forceinline__ void mma_f16(float d[4], const uint32_t a[4],
                                        const uint32_t b[2]) {
    asm volatile(
        "mma.sync.aligned.m16n8k16.row.col.f32.f16.f16.f32 "
        "{%0,%1,%2,%3}, {%4,%5,%6,%7}, {%8,%9}, {%0,%1,%2,%3};\n"
        : "+f"(d[0]), "+f"(d[1]), "+f"(d[2]), "+f"(d[3])
        : "r"(a[0]), "r"(a[1]), "r"(a[2]), "r"(a[3]), "r"(b[0]), "r"(b[1]));
}
// fp16 inputs, fp16 accumulate (C frag = 2 x f16x2 regs)
__device__ __forceinline__ void mma_f16acc(uint32_t d[2], const uint32_t a[4],
                                           const uint32_t b[2]) {
    asm volatile(
        "mma.sync.aligned.m16n8k16.row.col.f16.f16.f16.f16 "
        "{%0,%1}, {%2,%3,%4,%5}, {%6,%7}, {%0,%1};\n"
        : "+r"(d[0]), "+r"(d[1])
        : "r"(a[0]), "r"(a[1]), "r"(a[2]), "r"(a[3]), "r"(b[0]), "r"(b[1]));
}
__device__ __forceinline__ void ldmx4(uint32_t r[4], uint32_t addr) {
    asm volatile("ldmatrix.sync.aligned.m8n8.x4.shared.b16 {%0,%1,%2,%3}, [%4];"
                 : "=r"(r[0]), "=r"(r[1]), "=r"(r[2]), "=r"(r[3]) : "r"(addr));
}
__device__ __forceinline__ void ldmx4t(uint32_t r[4], uint32_t addr) {
    asm volatile("ldmatrix.sync.aligned.m8n8.x4.trans.shared.b16 {%0,%1,%2,%3}, [%4];"
                 : "=r"(r[0]), "=r"(r[1]), "=r"(r[2]), "=r"(r[3]) : "r"(addr));
}
__device__ __forceinline__ void cpa16(uint32_t dst, const void* src) {
    asm volatile("cp.async.cg.shared.global [%0], [%1], 16;\n"
                 :: "r"(dst), "l"(src));
}
#define CP_COMMIT() asm volatile("cp.async.commit_group;\n" ::)
#define CP_WAIT(n)  asm volatile("cp.async.wait_group %0;\n" :: "n"(n))

// ---------------------------------------------------------------------------
// All four weight conversions in ONE launch (fp32 -> fp16)
// ---------------------------------------------------------------------------
__global__ void cvt_all(const float* __restrict__ wqkvA,
                        const float* __restrict__ wqkvB,
                        const float* __restrict__ woutA,
                        const float* __restrict__ woutB,
                        __half* __restrict__ dq,
                        __half* __restrict__ do_) {
    int i = blockIdx.x * blockDim.x + threadIdx.x;
    const int QW = 3 * CC * CC / 4;
    const int OW = CC * CC / 4;
    const float* s; __half* d; int off;
    if (i < QW)               { s = wqkvA; d = dq;               off = i; }
    else if (i < 2 * QW)      { s = wqkvB; d = dq + 4 * QW;      off = i - QW; }
    else if (i < 2 * QW + OW) { s = woutA; d = do_;              off = i - 2 * QW; }
    else                      { s = woutB; d = do_ + 4 * OW;     off = i - 2 * QW - OW; }
    float4 v = ((const float4*)s)[off];
    *(uint2*)(d + (size_t)off * 4) = make_uint2(packh(v.x, v.y), packh(v.z, v.w));
}

// ---------------------------------------------------------------------------
// GroupNorm, both branches in one launch; writes fp16 ONLY (residual is
// taken from the same fp16 buffer in the proj epilogue).
// ---------------------------------------------------------------------------
__global__ void groupnorm_kernel(const float* __restrict__ x0,
                                 const float* __restrict__ x1,
                                 const float* __restrict__ gm0,
                                 const float* __restrict__ gm1,
                                 const float* __restrict__ bt0,
                                 const float* __restrict__ bt1,
                                 __half* __restrict__ outh) {
    int br = blockIdx.y;
    const float* x     = br ? x1 : x0;
    const float* gamma = br ? gm1 : gm0;
    const float* beta  = br ? bt1 : bt0;
    size_t broff = (size_t)br * BSZ * CC * SSZ;

    int bg = blockIdx.x;
    int b = bg / NG, g = bg % NG;
    const int n = CPG * SSZ;
    size_t off = broff + (size_t)(b * CC + g * CPG) * SSZ;
    int tid = threadIdx.x;

    const float4* x4 = (const float4*)(x + (size_t)(b * CC + g * CPG) * SSZ);
    float4 xv[16];
    float s = 0.f, s2 = 0.f;
    #pragma unroll
    for (int r = 0; r < 16; r++) {
        float4 v = x4[tid + r * 256];
        xv[r] = v;
        s  += v.x + v.y + v.z + v.w;
        s2 += v.x * v.x + v.y * v.y + v.z * v.z + v.w * v.w;
    }
    __shared__ float rs[256], rs2[256];
    rs[tid] = s; rs2[tid] = s2;
    __syncthreads();
    for (int o = 128; o > 0; o >>= 1) {
        if (tid < o) { rs[tid] += rs[tid + o]; rs2[tid] += rs2[tid + o]; }
        __syncthreads();
    }
    float mu = rs[0] / (float)n;
    float var = rs2[0] / (float)n - mu * mu;
    float rstd = rsqrtf(var + EPSV);

    __half* oh = outh + off;
    #pragma unroll
    for (int r = 0; r < 16; r++) {
        int i = tid + r * 256;
        int c = g * CPG + (i >> 8);
        float sc = gamma[c] * rstd;
        float sh = beta[c] - mu * sc;
        float4 v = xv[r];
        *(uint2*)(oh + (size_t)i * 4) =
            make_uint2(packh(v.x * sc + sh, v.y * sc + sh),
                       packh(v.z * sc + sh, v.w * sc + sh));
    }
}

// ---------------------------------------------------------------------------
// fp16 GEMM, cp.async 3-stage. C = A[Mx256]*B[256x1024]. z = branch*16+batch.
// EPI: +bias+residual(fp16), fp32 out. !EPI: Q rows pre-scaled, fp16 out.
// ---------------------------------------------------------------------------
#define GA_BYTES (128 * 80)
#define GB_BYTES (32 * 272)
#define GBUF (GA_BYTES + GB_BYTES)
#define GEMM_SMEM (3 * GBUF)

__device__ __forceinline__ void gemm_stage(uint32_t sbuf,
                                           const __half* A,
                                           const __half* Bp,
                                           int m0, int n0, int k0, int tid) {
    #pragma unroll
    for (int r = 0; r < 2; r++) {
        int idx = tid + r * 256;
        int row = idx >> 2, ch = idx & 3;
        cpa16(sbuf + row * 80 + ch * 16,
              A + (size_t)(m0 + row) * 256 + k0 + ch * 8);
    }
    #pragma unroll
    for (int r = 0; r < 2; r++) {
        int idx = tid + r * 256;
        int krow = idx >> 4, ch = idx & 15;
        cpa16(sbuf + GA_BYTES + krow * 272 + ch * 16,
              Bp + (size_t)(k0 + krow) * 1024 + n0 + ch * 8);
    }
}

template <bool EPI>
__global__ __launch_bounds__(256, 2) void gemm_f16(
    const __half* __restrict__ A0, const __half* __restrict__ A1,
    const __half* __restrict__ B0, const __half* __restrict__ B1,
    void* __restrict__ C0, void* __restrict__ C1,
    const float* __restrict__ bias0, const float* __restrict__ bias1,
    const __half* __restrict__ res0, const __half* __restrict__ res1,
    long strideB, long strideC) {
    const int N = 1024;
    int z = blockIdx.z;
    int br = z >> 4, bz = z & 15;
    const __half* A = br ? A1 : A0;
    const __half* Bp = (br ? B1 : B0) + (size_t)bz * strideB;
    int m0 = blockIdx.y * 128, n0 = blockIdx.x * 128;

    extern __shared__ __align__(16) uint8_t smem[];
    uint32_t sbase = (uint32_t)__cvta_generic_to_shared(smem);

    int tid = threadIdx.x;
    int lane = tid & 31, wid = tid >> 5;
    int wy = wid >> 2, wx = wid & 3;
    int lq = lane >> 2, lr = lane & 3;
    int l7 = lane & 7, lb = (lane >> 3) & 1, lhi = lane >> 4;

    float acc[4][4][4];
    #pragma unroll
    for (int i = 0; i < 4; i++)
        #pragma unroll
        for (int j = 0; j < 4; j++)
            #pragma unroll
            for (int c = 0; c < 4; c++) acc[i][j][c] = 0.f;

    gemm_stage(sbase, A, Bp, m0, n0, 0, tid);  CP_COMMIT();
    gemm_stage(sbase + GBUF, A, Bp, m0, n0, 32, tid);  CP_COMMIT();

    #pragma unroll
    for (int it = 0; it < 8; it++) {
        if (it == 7) { CP_WAIT(0); } else { CP_WAIT(1); }
        __syncthreads();
        if (it < 6) {
            gemm_stage(sbase + ((it + 2) % 3) * GBUF, A, Bp, m0, n0,
                       (it + 2) * 32, tid);
            CP_COMMIT();
        }
        uint32_t sA = sbase + (it % 3) * GBUF;
        uint32_t sB = sA + GA_BYTES;
        #pragma unroll
        for (int kk = 0; kk < 2; kk++) {
            uint32_t af[4][4], bf[2][4];
            #pragma unroll
            for (int mi = 0; mi < 4; mi++) {
                int row = wy * 64 + mi * 16 + l7 + lb * 8;
                int col = kk * 16 + lhi * 8;
                ldmx4(af[mi], sA + row * 80 + col * 2);
            }
            #pragma unroll
            for (int njp = 0; njp < 2; njp++) {
                int row = kk * 16 + l7 + lb * 8;
                int col = wx * 32 + njp * 16 + lhi * 8;
                ldmx4t(bf[njp], sB + row * 272 + col * 2);
            }
            #pragma unroll
            for (int mi = 0; mi < 4; mi++)
                #pragma unroll
                for (int njp = 0; njp < 2; njp++) {
                    mma_f16(acc[mi][njp * 2],     af[mi], &bf[njp][0]);
                    mma_f16(acc[mi][njp * 2 + 1], af[mi], &bf[njp][2]);
                }
        }
    }

    if (EPI) {
        float* Cp = (float*)(br ? C1 : C0) + (size_t)bz * strideC;
        const float* bias = br ? bias1 : bias0;
        const __half* Rp = (br ? res1 : res0) + (size_t)bz * strideB;
        #pragma unroll
        for (int mi = 0; mi < 4; mi++) {
            #pragma unroll
            for (int nj = 0; nj < 4; nj++) {
                int m = m0 + wy * 64 + mi * 16 + lq;
                int col = n0 + wx * 32 + nj * 8 + (lr << 1);
                float b0 = bias[m], b1 = bias[m + 8];
                __half2 rh0 = *(const __half2*)(Rp + (size_t)m * N + col);
                __half2 rh1 = *(const __half2*)(Rp + (size_t)(m + 8) * N + col);
                float2 r0 = __half22float2(rh0);
                float2 r1 = __half22float2(rh1);
                *(float2*)(Cp + (size_t)m * N + col) =
                    make_float2(acc[mi][nj][0] + b0 + r0.x,
                                acc[mi][nj][1] + b0 + r0.y);
                *(float2*)(Cp + (size_t)(m + 8) * N + col) =
                    make_float2(acc[mi][nj][2] + b1 + r1.x,
                                acc[mi][nj][3] + b1 + r1.y);
            }
        }
    } else {
        __half* Cp = (__half*)(br ? C1 : C0) + (size_t)bz * strideC;
        #pragma unroll
        for (int mi = 0; mi < 4; mi++) {
            #pragma unroll
            for (int nj = 0; nj < 4; nj++) {
                int m = m0 + wy * 64 + mi * 16 + lq;
                int col = n0 + wx * 32 + nj * 8 + (lr << 1);
                float q0 = ((m % 96) < 32) ? QSC : 1.f;
                float q1 = (((m + 8) % 96) < 32) ? QSC : 1.f;
                *(uint32_t*)(Cp + (size_t)m * N + col) =
                    packh(acc[mi][nj][0] * q0, acc[mi][nj][1] * q0);
                *(uint32_t*)(Cp + (size_t)(m + 8) * N + col) =
                    packh(acc[mi][nj][2] * q1, acc[mi][nj][3] * q1);
            }
        }
    }
}

// ---------------------------------------------------------------------------
// fp16 flash attention (R13 configuration — measured best): fused chunks,
// f16-acc S-GEMM, in-place ex2.f16x2, l via ones-column MMA, 3 CTAs/SM.
// ---------------------------------------------------------------------------
#define ATT_T   8704
#define ATT_SMEM (ATT_T + 3 * 2 * ATT_T)

__device__ __forceinline__ void attn_stage_kv(uint32_t sK,
                                              const __half* Kg,
                                              const __half* Vg,
                                              int k0c, int tid) {
    #pragma unroll
    for (int r = 0; r < 2; r++) {
        int idx = tid + r * 256;
        int row = idx >> 4, ch = idx & 15;
        cpa16(sK + row * 272 + ch * 16,
              Kg + (size_t)row * SSZ + k0c + ch * 8);
        cpa16(sK + ATT_T + row * 272 + ch * 16,
              Vg + (size_t)row * SSZ + k0c + ch * 8);
    }
}

__global__ __launch_bounds__(256, 3) void attn_f16(
    const __half* __restrict__ qkvA,
    const __half* __restrict__ qkvB,
    __half* __restrict__ attnA,
    __half* __restrict__ attnB) {
    extern __shared__ __align__(16) uint8_t smraw[];
    uint32_t sQ = (uint32_t)__cvta_generic_to_shared(smraw);

    int brz = blockIdx.z;
    const __half* qsrc = brz ? qkvA : qkvB;
    const __half* kvsrc = brz ? qkvB : qkvA;
    __half* outh = brz ? attnB : attnA;

    int qt = blockIdx.x;
    int bh = blockIdx.y;
    int b = bh >> 3, h = bh & 7;
    size_t base = (size_t)b * 3 * CC * SSZ + (size_t)h * 96 * SSZ;
    const __half* Qg = qsrc  + base;
    const __half* Kg = kvsrc + base + 32 * SSZ;
    const __half* Vg = kvsrc + base + 64 * SSZ;

    int tid = threadIdx.x;
    int lane = tid & 31, wid = tid >> 5;
    int lq = lane >> 2, lr = lane & 3;
    int l7 = lane & 7, lb = (lane >> 3) & 1, lhi = lane >> 4;
    int q0 = qt * 128;

    #pragma unroll
    for (int r = 0; r < 2; r++) {
        int idx = tid + r * 256;
        int row = idx >> 4, ch = idx & 15;
        cpa16(sQ + row * 272 + ch * 16, Qg + (size_t)row * SSZ + q0 + ch * 8);
    }
    attn_stage_kv(sQ + ATT_T, Kg, Vg, 0, tid);
    CP_COMMIT();
    attn_stage_kv(sQ + ATT_T + 2 * ATT_T, Kg, Vg, 128, tid);
    CP_COMMIT();

    CP_WAIT(1);
    __syncthreads();
    uint32_t qf[2][4];
    #pragma unroll
    for (int kk = 0; kk < 2; kk++) {
        int row = kk * 16 + l7 + lhi * 8;        // d
        int col = wid * 16 + lb * 8;             // q
        ldmx4t(qf[kk], sQ + row * 272 + col * 2);
    }

    // ones B-fragment for l-column MMA (fp16 1.0 pairs on lq==0 lanes)
    uint32_t onesb = (lq == 0) ? 0x3C003C00u : 0u;
    uint32_t onesv[2] = {onesb, onesb};

    float lacc[4] = {0.f, 0.f, 0.f, 0.f};
    float oacc[4][4];
    #pragma unroll
    for (int j = 0; j < 4; j++)
        #pragma unroll
        for (int c = 0; c < 4; c++) oacc[j][c] = 0.f;

    for (int kt = 0; kt < 8; kt++) {
        if (kt > 0) {
            if (kt == 7) { CP_WAIT(0); } else { CP_WAIT(1); }
            __syncthreads();
        }
        if (kt < 6) {
            attn_stage_kv(sQ + ATT_T + ((kt + 2) % 3) * 2 * ATT_T,
                          Kg, Vg, (kt + 2) * 128, tid);
            CP_COMMIT();
        }
        uint32_t sK = sQ + ATT_T + (kt % 3) * 2 * ATT_T;
        uint32_t sV = sK + ATT_T;

        #pragma unroll
        for (int njp = 0; njp < 8; njp++) {
            uint32_t s0[2] = {0u, 0u};
            uint32_t s1[2] = {0u, 0u};
            #pragma unroll
            for (int kk = 0; kk < 2; kk++) {
                uint32_t kf[4];
                int krow = kk * 16 + l7 + lb * 8;
                int col = njp * 16 + lhi * 8;
                ldmx4t(kf, sK + krow * 272 + col * 2);
                mma_f16acc(s0, qf[kk], &kf[0]);
                mma_f16acc(s1, qf[kk], &kf[2]);
            }
            // p = 2^s directly in f16x2: S C-frag IS the O A-frag layout
            uint32_t af[4];
            af[0] = ex2h2(s0[0]);
            af[1] = ex2h2(s0[1]);
            af[2] = ex2h2(s1[0]);
            af[3] = ex2h2(s1[1]);

            int col = njp * 16 + lb * 8;         // kpos
            int rbase = l7 + lhi * 8;            // d
            uint32_t vf0[4], vf1[4];
            ldmx4(vf0, sV + rbase * 272 + col * 2);
            ldmx4(vf1, sV + (rbase + 16) * 272 + col * 2);
            mma_f16(oacc[0], af, &vf0[0]);
            mma_f16(oacc[1], af, &vf0[2]);
            mma_f16(oacc[2], af, &vf1[0]);
            mma_f16(oacc[3], af, &vf1[2]);
            mma_f16(lacc, af, onesv);            // l += P * ones
        }
    }

    // l lives in lacc[0] (row lq) / lacc[2] (row lq+8) of each quad's lr==0
    int src = lane & ~3;
    float l0 = __shfl_sync(0xffffffffu, lacc[0], src);
    float l1 = __shfl_sync(0xffffffffu, lacc[2], src);
    float il0 = 1.f / l0, il1 = 1.f / l1;

    __half* O16 = (__half*)smraw;   // [32][136]
    int r0g = wid * 16 + lq;
    __syncthreads();
    #pragma unroll
    for (int nj = 0; nj < 4; nj++) {
        int d0 = nj * 8 + (lr << 1);
        O16[d0 * 136 + r0g]           = __float2half(oacc[nj][0] * il0);
        O16[(d0 + 1) * 136 + r0g]     = __float2half(oacc[nj][1] * il0);
        O16[d0 * 136 + r0g + 8]       = __float2half(oacc[nj][2] * il1);
        O16[(d0 + 1) * 136 + r0g + 8] = __float2half(oacc[nj][3] * il1);
    }
    __syncthreads();
    #pragma unroll
    for (int r = 0; r < 2; r++) {
        int idx = tid + r * 256;
        int row = idx >> 4, ch = idx & 15;
        *(uint4*)(outh + ((size_t)b * CC + h * 32 + row) * SSZ + q0 + ch * 8) =
            *(uint4*)&O16[row * 136 + ch * 8];
    }
}

// ---------------------------------------------------------------------------
extern "C" void kernel_launch(void* const* d_in, const int* in_sizes, int n_in,
                              void* d_out, int out_size) {
    const float* xA    = (const float*)d_in[0];
    const float* xB    = (const float*)d_in[1];
    const float* gA    = (const float*)d_in[2];
    const float* bA    = (const float*)d_in[3];
    const float* gB    = (const float*)d_in[4];
    const float* bB    = (const float*)d_in[5];
    const float* WqkvA = (const float*)d_in[6];
    const float* WqkvB = (const float*)d_in[7];
    const float* WoutA = (const float*)d_in[8];
    const float* boutA = (const float*)d_in[9];
    const float* WoutB = (const float*)d_in[10];
    const float* boutB = (const float*)d_in[11];
    float* out = (float*)d_out;

    void *pnh, *pq, *pa, *pw;
    cudaGetSymbolAddress(&pnh, g_normh);
    cudaGetSymbolAddress(&pq,  g_qkvh);
    cudaGetSymbolAddress(&pa,  g_attnh);
    cudaGetSymbolAddress(&pw,  g_wh);
    __half* normhA = (__half*)pnh;
    __half* normhB = normhA + (size_t)BSZ * CC * SSZ;
    __half* qkvA = (__half*)pq;
    __half* qkvB = qkvA + (size_t)BSZ * 3 * CC * SSZ;
    __half* attnA = (__half*)pa;
    __half* attnB = attnA + (size_t)BSZ * CC * SSZ;
    __half* wqA = (__half*)pw;
    __half* wqB = wqA + 3 * CC * CC;
    __half* woA = wqB + 3 * CC * CC;
    __half* woB = woA + CC * CC;

    const long CS = (long)CC * SSZ;
    const long Q3 = (long)3 * CC * SSZ;

    cudaFuncSetAttribute(gemm_f16<false>,
                         cudaFuncAttributeMaxDynamicSharedMemorySize, GEMM_SMEM);
    cudaFuncSetAttribute(gemm_f16<true>,
                         cudaFuncAttributeMaxDynamicSharedMemorySize, GEMM_SMEM);
    cudaFuncSetAttribute(attn_f16,
                         cudaFuncAttributeMaxDynamicSharedMemorySize, ATT_SMEM);

    cvt_all<<<512, 256>>>(WqkvA, WqkvB, WoutA, WoutB, wqA, woA);

    dim3 gn(BSZ * NG, 2);
    groupnorm_kernel<<<gn, 256>>>(xA, xB, gA, gB, bA, bB, (__half*)pnh);

    dim3 gq(8, 6, 32);
    gemm_f16<false><<<gq, 256, GEMM_SMEM>>>(
        wqA, wqB, normhA, normhB, qkvA, qkvB,
        nullptr, nullptr, nullptr, nullptr, CS, Q3);

    dim3 ga(8, BSZ * NHD, 2);
    attn_f16<<<ga, 256, ATT_SMEM>>>(qkvA, qkvB, attnA, attnB);

    dim3 gp(8, 2, 32);
    gemm_f16<true><<<gp, 256, GEMM_SMEM>>>(
        woA, woB, attnA, attnB, out, out + (size_t)BSZ * CC * SSZ,
        boutA, boutB, normhA, normhB, CS, CS);
}